// round 5
// baseline (speedup 1.0000x reference)
#include <cuda_runtime.h>
#include <cuda_bf16.h>
#include <math.h>

#define Nn 2048
#define Dd 512
#define M_LZ 256
#define NB 148              // persistent blocks (<= 152 SMs, 1 CTA/SM -> co-resident)
#define NT 256
#define NWARP ((NB * NT) / 32)   // 1184 global warps
#ifndef SIGN_CONV
#define SIGN_CONV (-1.0)
#endif

// ---------------- device scratch (static; no runtime allocation) -------------
__device__ float g_q[Nn];
__device__ float g_deg[Nn];
__device__ float g_V[(M_LZ + 1) * Nn];  // row 0 = ones/sqrt(N); rows 1..M Lanczos basis
__device__ float g_w[Nn];               // raw (unnormalized) candidate vector w_j
__device__ float g_ub[Nn];              // ubar = L * w_raw (unscaled)
__device__ float g_u[Nn];               // u after scaling / pass-1 subtraction
__device__ float g_c1[M_LZ + 2];
__device__ float g_c2[M_LZ + 2];
__device__ float g_alpha[M_LZ + 2];     // T diagonal (1-based)
__device__ float g_beta2[M_LZ + 2];     // ||w_{j-1}||^2 (1-based: beta2[j] = |w entering iter j|^2)
__device__ float g_mean;
__device__ double g_yd[M_LZ];           // tridiagonal eigenvector
__device__ float g_fv[Nn];              // assembled Fiedler vector (unnormalized)
__device__ float g_z[Nn];               // z = L * fv
// software grid barrier state (self-resetting across graph replays)
__device__ volatile unsigned g_gen;
__device__ unsigned g_cnt;

// ---------------- reduction helpers ------------------------------------------
__device__ __forceinline__ float warpReduceSumF(float v) {
#pragma unroll
    for (int o = 16; o; o >>= 1) v += __shfl_down_sync(0xffffffffu, v, o);
    return v;
}
__device__ __forceinline__ double warpReduceSumD(double v) {
#pragma unroll
    for (int o = 16; o; o >>= 1) v += __shfl_down_sync(0xffffffffu, v, o);
    return v;
}
__device__ __forceinline__ float blockReduceSumF(float v, float* sh) {
    int lane = threadIdx.x & 31, wid = threadIdx.x >> 5;
    v = warpReduceSumF(v);
    __syncthreads();
    if (lane == 0) sh[wid] = v;
    __syncthreads();
    if (wid == 0) {
        int nw = (blockDim.x + 31) >> 5;
        float s = (lane < nw) ? sh[lane] : 0.f;
        s = warpReduceSumF(s);
        if (lane == 0) sh[0] = s;
    }
    __syncthreads();
    return sh[0];
}
__device__ __forceinline__ double blockReduceSumD(double v, double* sh) {
    int lane = threadIdx.x & 31, wid = threadIdx.x >> 5;
    v = warpReduceSumD(v);
    __syncthreads();
    if (lane == 0) sh[wid] = v;
    __syncthreads();
    if (wid == 0) {
        int nw = (blockDim.x + 31) >> 5;
        double s = (lane < nw) ? sh[lane] : 0.0;
        s = warpReduceSumD(s);
        if (lane == 0) sh[0] = s;
    }
    __syncthreads();
    return sh[0];
}

__device__ __forceinline__ float sigmoidf_(float s) {
    if (s >= 0.f) { float ez = __expf(-s); return 1.f / (1.f + ez); }
    float ez = __expf(s); return ez / (1.f + ez);
}

// grid-wide barrier; all NB blocks co-resident; generation counter never resets
__device__ __forceinline__ void gbar() {
    __syncthreads();
    if (threadIdx.x == 0) {
        __threadfence();
        unsigned gen = g_gen;
        if (atomicAdd(&g_cnt, 1u) == NB - 1u) {
            g_cnt = 0;
            __threadfence();
            g_gen = gen + 1;
        } else {
            while (g_gen == gen) { __nanosleep(32); }
        }
        __threadfence();
    }
    __syncthreads();
}

// ---------------- q_i = sum_k w_k x_ik^2 -------------------------------------
__global__ void k_q(const float* __restrict__ x, const float* __restrict__ w) {
    __shared__ float sh[4];
    int i = blockIdx.x, tid = threadIdx.x;
    float acc = 0.f;
    for (int k = tid; k < Dd; k += 128) {
        float xv = x[(size_t)i * Dd + k];
        acc = fmaf(w[k] * xv, xv, acc);
    }
    acc = blockReduceSumF(acc, sh);
    if (tid == 0) g_q[i] = acc;
}

// ---------------- G = sigmoid(q_i + q_j - 2*X diag(w) X^T + b) ---------------
__global__ void k_gemm(const float* __restrict__ x, const float* __restrict__ w,
                       const float* __restrict__ bptr, float* __restrict__ G) {
    __shared__ float As[16][132];
    __shared__ float Bs[16][132];
    int bm = blockIdx.y * 128, bn = blockIdx.x * 128;
    int tid = threadIdx.x;
    int tx = tid & 15, ty = tid >> 4;
    float acc[8][8];
#pragma unroll
    for (int i = 0; i < 8; i++)
#pragma unroll
        for (int j = 0; j < 8; j++) acc[i][j] = 0.f;

    for (int k0 = 0; k0 < Dd; k0 += 16) {
#pragma unroll
        for (int s = 0; s < 8; s++) {
            int li = tid + s * 256;
            int r = li >> 4, kk = li & 15;
            As[kk][r] = x[(size_t)(bm + r) * Dd + k0 + kk] * w[k0 + kk];
            Bs[kk][r] = x[(size_t)(bn + r) * Dd + k0 + kk];
        }
        __syncthreads();
#pragma unroll
        for (int kk = 0; kk < 16; kk++) {
            float a[8], bb[8];
#pragma unroll
            for (int i = 0; i < 8; i++) a[i] = As[kk][ty * 8 + i];
#pragma unroll
            for (int j = 0; j < 8; j++) bb[j] = Bs[kk][tx * 8 + j];
#pragma unroll
            for (int i = 0; i < 8; i++)
#pragma unroll
                for (int j = 0; j < 8; j++) acc[i][j] = fmaf(a[i], bb[j], acc[i][j]);
        }
        __syncthreads();
    }
    float bv = bptr[0];
#pragma unroll
    for (int i = 0; i < 8; i++) {
        int row = bm + ty * 8 + i;
        float qi = g_q[row] + bv;
#pragma unroll
        for (int j = 0; j < 8; j += 4) {
            int col = bn + tx * 8 + j;
            float4 o;
            o.x = sigmoidf_(qi + g_q[col + 0] - 2.f * acc[i][j + 0]);
            o.y = sigmoidf_(qi + g_q[col + 1] - 2.f * acc[i][j + 1]);
            o.z = sigmoidf_(qi + g_q[col + 2] - 2.f * acc[i][j + 2]);
            o.w = sigmoidf_(qi + g_q[col + 3] - 2.f * acc[i][j + 3]);
            *reinterpret_cast<float4*>(&G[(size_t)row * Nn + col]) = o;
        }
    }
}

// ---------------- degree = row sums of G -------------------------------------
__global__ void k_rowsum(const float* __restrict__ G) {
    __shared__ float sh[8];
    int i = blockIdx.x, tid = threadIdx.x;
    const float* row = G + (size_t)i * Nn;
    float acc = 0.f;
    for (int t = tid; t < Nn; t += 256) acc += row[t];
    acc = blockReduceSumF(acc, sh);
    if (tid == 0) g_deg[i] = acc;
}

// ---------------- persistent Lanczos (entire m-step loop, 1 kernel) ----------
__global__ void __launch_bounds__(NT) k_lanczos(const float* __restrict__ G) {
    const int tid = threadIdx.x;
    const int gid = blockIdx.x * NT + tid;
    const int gw = gid >> 5, lane = gid & 31;

    // ---- init phase: zero scalars, build v1 = hash - mean, V0 = ones/sqrt(N)
    float r = 0.f;
    if (gid < Nn) {
        unsigned u = (unsigned)(gid + 1) * 2654435761u;
        u ^= u >> 16; u *= 2246822519u; u ^= u >> 13; u *= 3266489917u; u ^= u >> 16;
        r = (float)(u & 0xFFFFFFu) * (1.f / 16777216.f) - 0.5f;
        g_V[gid] = rsqrtf((float)Nn);
    }
    if (gid < M_LZ + 2) g_beta2[gid] = 0.f;
    if (gid == 0) g_mean = 0.f;
    gbar();
    if (gw < Nn / 32) {
        float s = warpReduceSumF(r);
        if (lane == 0) atomicAdd(&g_mean, s);
    }
    gbar();
    if (gid < Nn) g_w[gid] = r - g_mean * (1.f / (float)Nn);
    gbar();

    for (int j = 1; j <= M_LZ; j++) {
        // ---- Phase A: ubar = deg.*w - G*w (raw w); beta2[j] = ||w||^2
        if (gid < Nn) {
            float wv = g_w[gid];
            float p = warpReduceSumF(wv * wv);
            if (lane == 0) atomicAdd(&g_beta2[j], p);
        }
        for (int row = gw; row < Nn; row += NWARP) {
            const float* Gr = G + (size_t)row * Nn;
            float acc = 0.f;
#pragma unroll 4
            for (int t = lane; t < Nn; t += 32) acc = fmaf(Gr[t], g_w[t], acc);
            acc = warpReduceSumF(acc);
            if (lane == 0) g_ub[row] = g_deg[row] * g_w[row] - acc;
        }
        gbar();

        // ---- Phase B: commit V[j] = w*invb; u = ubar*invb; dots1 (scaled)
        float invb = rsqrtf(fmaxf(g_beta2[j], 1e-30f));
        if (gid < Nn) {
            float wv = g_w[gid];
            g_V[(size_t)j * Nn + gid] = wv * invb;
            g_u[gid] = g_ub[gid] * invb;
        }
        if (gw <= j) {
            float acc = 0.f;
            if (gw == j) {
#pragma unroll 4
                for (int t = lane; t < Nn; t += 32) acc = fmaf(g_w[t], g_ub[t], acc);
                acc = warpReduceSumF(acc) * (invb * invb);
            } else {
                const float* vi = g_V + (size_t)gw * Nn;
#pragma unroll 4
                for (int t = lane; t < Nn; t += 32) acc = fmaf(vi[t], g_ub[t], acc);
                acc = warpReduceSumF(acc) * invb;
            }
            if (lane == 0) g_c1[gw] = acc;
        }
        gbar();

        // ---- Phase C: u -= sum_i c1_i V_i (16 stripes, atomics)
        {
            int s = gid >> 11, t = gid & (Nn - 1);
            if (gid < 16 * Nn) {
                float part = 0.f;
#pragma unroll 4
                for (int i = s; i <= j; i += 16)
                    part = fmaf(g_c1[i], g_V[(size_t)i * Nn + t], part);
                if (part != 0.f) atomicAdd(&g_u[t], -part);
            }
        }
        gbar();

        // ---- Phase D: dots2; pre-seed w = u
        if (gid < Nn) g_w[gid] = g_u[gid];
        if (gw <= j) {
            const float* vi = g_V + (size_t)gw * Nn;
            float acc = 0.f;
#pragma unroll 4
            for (int t = lane; t < Nn; t += 32) acc = fmaf(vi[t], g_u[t], acc);
            acc = warpReduceSumF(acc);
            if (lane == 0) g_c2[gw] = acc;
        }
        gbar();

        // ---- Phase E: w -= sum_i c2_i V_i; alpha_j = c1_j + c2_j
        {
            int s = gid >> 11, t = gid & (Nn - 1);
            if (gid < 16 * Nn) {
                float part = 0.f;
#pragma unroll 4
                for (int i = s; i <= j; i += 16)
                    part = fmaf(g_c2[i], g_V[(size_t)i * Nn + t], part);
                if (part != 0.f) atomicAdd(&g_w[t], -part);
            }
            if (gid == 0) g_alpha[j] = g_c1[j] + g_c2[j];
        }
        gbar();
    }
}

// ---------------- smallest eigenpair of T (m=256 tridiagonal), one warp -------
__global__ void k_tridiag() {
    __shared__ double aa[M_LZ], bb2[M_LZ], bb[M_LZ];
    __shared__ double dw[M_LZ], ew[M_LZ], fw[M_LZ], yv[M_LZ], rv[M_LZ];
    __shared__ double sx[32];
    __shared__ int scnt[32];
    __shared__ double slo, shi;
    int lane = threadIdx.x;
    for (int i = lane; i < M_LZ; i += 32) {
        aa[i] = (double)g_alpha[i + 1];
        double b2 = (i < M_LZ - 1) ? (double)g_beta2[i + 2] : 0.0;
        bb2[i] = b2;
        bb[i] = sqrt(b2);
    }
    __syncwarp();
    if (lane == 0) {
        double lo = 1e300, hi = -1e300;
        for (int i = 0; i < M_LZ; i++) {
            double bl = (i > 0) ? bb[i - 1] : 0.0;
            double br = (i < M_LZ - 1) ? bb[i] : 0.0;
            lo = fmin(lo, aa[i] - bl - br);
            hi = fmax(hi, aa[i] + bl + br);
        }
        slo = lo - 1.0; shi = hi + 1.0;
    }
    __syncwarp();
    for (int round = 0; round < 8; round++) {
        double lo = slo, hi = shi;
        double x = lo + (hi - lo) * (double)(lane + 1) * (1.0 / 33.0);
        double d = aa[0] - x;
        int cnt = (d < 0.0);
        for (int i = 1; i < M_LZ; i++) {
            if (fabs(d) < 1e-280) d = (d < 0.0 ? -1e-280 : 1e-280);
            d = aa[i] - x - bb2[i - 1] / d;
            cnt += (d < 0.0);
        }
        sx[lane] = x; scnt[lane] = cnt;
        __syncwarp();
        if (lane == 0) {
            double nlo = lo, nhi = hi;
            int k = 0;
            while (k < 32 && scnt[k] < 1) k++;
            if (k < 32) { nhi = sx[k]; if (k > 0) nlo = sx[k - 1]; }
            else        { nlo = sx[31]; }
            slo = nlo; shi = nhi;
        }
        __syncwarp();
    }
    double th = 0.5 * (slo + shi);
    if (lane == 0) {
        for (int i = 0; i < M_LZ; i++) rv[i] = 1.0;
        for (int it = 0; it < 3; it++) {
            for (int i = 0; i < M_LZ; i++) {
                dw[i] = aa[i] - th;
                ew[i] = (i < M_LZ - 1) ? bb[i] : 0.0;
                fw[i] = 0.0;
                yv[i] = rv[i];
            }
            for (int i = 0; i < M_LZ - 1; i++) {
                double s = bb[i];
                if (fabs(s) > fabs(dw[i])) {
                    double od = dw[i], oe = ew[i], of = fw[i];
                    dw[i] = s;       ew[i] = dw[i + 1]; fw[i] = ew[i + 1];
                    s = od;          dw[i + 1] = oe;    ew[i + 1] = of;
                    double ry = yv[i]; yv[i] = yv[i + 1]; yv[i + 1] = ry;
                }
                double p = dw[i];
                if (fabs(p) < 1e-280) { p = (p < 0.0 ? -1e-280 : 1e-280); dw[i] = p; }
                double m = s / p;
                dw[i + 1] -= m * ew[i];
                ew[i + 1] -= m * fw[i];
                yv[i + 1] -= m * yv[i];
            }
            for (int i = M_LZ - 1; i >= 0; i--) {
                double v = yv[i];
                if (i + 1 < M_LZ) v -= ew[i] * yv[i + 1];
                if (i + 2 < M_LZ) v -= fw[i] * yv[i + 2];
                double p = dw[i];
                if (fabs(p) < 1e-280) p = (p < 0.0 ? -1e-280 : 1e-280);
                yv[i] = v / p;
            }
            double n2 = 0.0;
            for (int i = 0; i < M_LZ; i++) n2 += yv[i] * yv[i];
            double inv = 1.0 / sqrt(n2);
            for (int i = 0; i < M_LZ; i++) rv[i] = yv[i] * inv;
        }
        for (int i = 0; i < M_LZ; i++) g_yd[i] = rv[i];
    }
}

// ---------------- fv = sum_r y_{r-1} V[r] -------------------------------------
__global__ void k_assemble() {
    int t = blockIdx.x * 256 + threadIdx.x;
    float acc = 0.f;
    for (int rr = 1; rr <= M_LZ; rr++)
        acc = fmaf((float)g_yd[rr - 1], g_V[(size_t)rr * Nn + t], acc);
    g_fv[t] = acc;
}

// ---------------- z = L * fv (fp32) -------------------------------------------
__global__ void k_rq(const float* __restrict__ G) {
    __shared__ float sh[8];
    int i = blockIdx.x, tid = threadIdx.x;
    const float* row = G + (size_t)i * Nn;
    float acc = 0.f;
    for (int t = tid; t < Nn; t += 256) acc = fmaf(row[t], g_fv[t], acc);
    acc = blockReduceSumF(acc, sh);
    if (tid == 0) g_z[i] = g_deg[i] * g_fv[i] - acc;
}

// ---------------- value = fv.z / fv.fv; normalize + sign + write --------------
__global__ void k_final(float* __restrict__ out) {
    __shared__ double sh[32];
    __shared__ float sabs[32];
    __shared__ int sidx[32];
    __shared__ double ssign;
    int tid = threadIdx.x;
    double a = (double)g_fv[tid], b = (double)g_fv[tid + 1024];
    double num = blockReduceSumD(a * (double)g_z[tid] + b * (double)g_z[tid + 1024], sh);
    double den = blockReduceSumD(a * a + b * b, sh);
    float bav; int bix;
    float fa = (float)fabs(a), fb = (float)fabs(b);
    if (fa >= fb) { bav = fa; bix = tid; }
    else          { bav = fb; bix = tid + 1024; }
#pragma unroll
    for (int o = 16; o; o >>= 1) {
        float ov = __shfl_down_sync(0xffffffffu, bav, o);
        int   oi = __shfl_down_sync(0xffffffffu, bix, o);
        if (ov > bav || (ov == bav && oi < bix)) { bav = ov; bix = oi; }
    }
    int lane = tid & 31, wid = tid >> 5;
    if (lane == 0) { sabs[wid] = bav; sidx[wid] = bix; }
    __syncthreads();
    if (tid == 0) {
        float bv = sabs[0]; int bi = sidx[0];
        for (int i = 1; i < 32; i++)
            if (sabs[i] > bv || (sabs[i] == bv && sidx[i] < bi)) { bv = sabs[i]; bi = sidx[i]; }
        ssign = (g_fv[bi] >= 0.f ? 1.0 : -1.0) * SIGN_CONV;
        out[(size_t)Nn * Nn] = (float)(num / fmax(den, 1e-300));
    }
    __syncthreads();
    double sc = ssign / sqrt(fmax(den, 1e-300));
    size_t base = (size_t)Nn * Nn + 1;
    out[base + tid]        = (float)(a * sc);
    out[base + tid + 1024] = (float)(b * sc);
}

// ---------------- launcher ----------------------------------------------------
extern "C" void kernel_launch(void* const* d_in, const int* in_sizes, int n_in,
                              void* d_out, int out_size) {
    const float* x = (const float*)d_in[0];
    const float* w = (const float*)d_in[1];
    const float* b = (const float*)d_in[2];
    float* out = (float*)d_out;
    float* G = out;   // grouping matrix lives at the front of d_out

    k_q<<<Nn, 128>>>(x, w);
    k_gemm<<<dim3(Nn / 128, Nn / 128), 256>>>(x, w, b, G);
    k_rowsum<<<Nn, 256>>>(G);
    k_lanczos<<<NB, NT>>>(G);
    k_tridiag<<<1, 32>>>();
    k_assemble<<<Nn / 256, 256>>>();
    k_rq<<<Nn, 256>>>(G);
    k_final<<<1, 1024>>>(out);
}

// round 6
// speedup vs baseline: 2.4588x; 2.4588x over previous
#include <cuda_runtime.h>
#include <cuda_bf16.h>
#include <math.h>

#define Nn 2048
#define Dd 512
#define M_LZ 128
#define NB 148              // persistent blocks (1 CTA/SM -> co-resident)
#define NT 256
#define NWARP ((NB * NT) / 32)   // 1184 global warps
#ifndef SIGN_CONV
#define SIGN_CONV (-1.0)
#endif

// ---------------- device scratch (static; no runtime allocation) -------------
__device__ float g_q[Nn];
__device__ float g_deg[Nn];
__device__ float g_V[(M_LZ + 1) * Nn];  // row 0 = ones/sqrt(N); rows 1..M Lanczos basis
__device__ float g_w[Nn];               // raw (unnormalized) candidate vector w_j
__device__ float g_ub[Nn];              // ubar = L * w_raw (unscaled)
__device__ float g_u[Nn];               // u after scaling / pass-1 subtraction
__device__ float g_c1[M_LZ + 2];
__device__ float g_c2[M_LZ + 2];
__device__ float g_alpha[M_LZ + 2];     // T diagonal (1-based)
__device__ float g_beta2[M_LZ + 2];     // ||w entering iter j||^2 (1-based)
__device__ float g_mean;
__device__ double g_yd[M_LZ];           // tridiagonal eigenvector
__device__ float g_fv[Nn];              // assembled Fiedler vector (unnormalized)
__device__ float g_z[Nn];               // z = L * fv
// two-level grid barrier state (self-resetting across graph replays)
__device__ unsigned g_cnt8[8 * 32];     // 8 group counters, 128B apart
__device__ unsigned g_root;
__device__ volatile unsigned g_gen;

// ---------------- reduction helpers ------------------------------------------
__device__ __forceinline__ float warpReduceSumF(float v) {
#pragma unroll
    for (int o = 16; o; o >>= 1) v += __shfl_down_sync(0xffffffffu, v, o);
    return v;
}
__device__ __forceinline__ double warpReduceSumD(double v) {
#pragma unroll
    for (int o = 16; o; o >>= 1) v += __shfl_down_sync(0xffffffffu, v, o);
    return v;
}
__device__ __forceinline__ float blockReduceSumF(float v, float* sh) {
    int lane = threadIdx.x & 31, wid = threadIdx.x >> 5;
    v = warpReduceSumF(v);
    __syncthreads();
    if (lane == 0) sh[wid] = v;
    __syncthreads();
    if (wid == 0) {
        int nw = (blockDim.x + 31) >> 5;
        float s = (lane < nw) ? sh[lane] : 0.f;
        s = warpReduceSumF(s);
        if (lane == 0) sh[0] = s;
    }
    __syncthreads();
    return sh[0];
}
__device__ __forceinline__ double blockReduceSumD(double v, double* sh) {
    int lane = threadIdx.x & 31, wid = threadIdx.x >> 5;
    v = warpReduceSumD(v);
    __syncthreads();
    if (lane == 0) sh[wid] = v;
    __syncthreads();
    if (wid == 0) {
        int nw = (blockDim.x + 31) >> 5;
        double s = (lane < nw) ? sh[lane] : 0.0;
        s = warpReduceSumD(s);
        if (lane == 0) sh[0] = s;
    }
    __syncthreads();
    return sh[0];
}

__device__ __forceinline__ float sigmoidf_(float s) {
    if (s >= 0.f) { float ez = __expf(-s); return 1.f / (1.f + ez); }
    float ez = __expf(s); return ez / (1.f + ez);
}

// grid-wide barrier; two-level arrival (8 groups), single-release
__device__ __forceinline__ void gbar() {
    __syncthreads();
    if (threadIdx.x == 0) {
        __threadfence();
        unsigned gen = g_gen;
        int grp = blockIdx.x & 7;
        unsigned gsz = (unsigned)(NB / 8) + ((unsigned)grp < (unsigned)(NB % 8) ? 1u : 0u);
        bool release = false;
        if (atomicAdd(&g_cnt8[grp * 32], 1u) == gsz - 1u) {
            g_cnt8[grp * 32] = 0;
            if (atomicAdd(&g_root, 1u) == 7u) {
                g_root = 0;
                __threadfence();
                g_gen = gen + 1;
                release = true;
            }
        }
        if (!release) {
            while (g_gen == gen) { __nanosleep(16); }
        }
        __threadfence();
    }
    __syncthreads();
}

// ---------------- q_i = sum_k w_k x_ik^2 -------------------------------------
__global__ void k_q(const float* __restrict__ x, const float* __restrict__ w) {
    __shared__ float sh[4];
    int i = blockIdx.x, tid = threadIdx.x;
    float acc = 0.f;
    for (int k = tid; k < Dd; k += 128) {
        float xv = x[(size_t)i * Dd + k];
        acc = fmaf(w[k] * xv, xv, acc);
    }
    acc = blockReduceSumF(acc, sh);
    if (tid == 0) g_q[i] = acc;
}

// ---------------- G = sigmoid(q_i + q_j - 2*X diag(w) X^T + b) ---------------
__global__ void k_gemm(const float* __restrict__ x, const float* __restrict__ w,
                       const float* __restrict__ bptr, float* __restrict__ G) {
    __shared__ float As[16][132];
    __shared__ float Bs[16][132];
    int bm = blockIdx.y * 128, bn = blockIdx.x * 128;
    int tid = threadIdx.x;
    int tx = tid & 15, ty = tid >> 4;
    float acc[8][8];
#pragma unroll
    for (int i = 0; i < 8; i++)
#pragma unroll
        for (int j = 0; j < 8; j++) acc[i][j] = 0.f;

    for (int k0 = 0; k0 < Dd; k0 += 16) {
#pragma unroll
        for (int s = 0; s < 8; s++) {
            int li = tid + s * 256;
            int r = li >> 4, kk = li & 15;
            As[kk][r] = x[(size_t)(bm + r) * Dd + k0 + kk] * w[k0 + kk];
            Bs[kk][r] = x[(size_t)(bn + r) * Dd + k0 + kk];
        }
        __syncthreads();
#pragma unroll
        for (int kk = 0; kk < 16; kk++) {
            float a[8], bb[8];
#pragma unroll
            for (int i = 0; i < 8; i++) a[i] = As[kk][ty * 8 + i];
#pragma unroll
            for (int j = 0; j < 8; j++) bb[j] = Bs[kk][tx * 8 + j];
#pragma unroll
            for (int i = 0; i < 8; i++)
#pragma unroll
                for (int j = 0; j < 8; j++) acc[i][j] = fmaf(a[i], bb[j], acc[i][j]);
        }
        __syncthreads();
    }
    float bv = bptr[0];
#pragma unroll
    for (int i = 0; i < 8; i++) {
        int row = bm + ty * 8 + i;
        float qi = g_q[row] + bv;
#pragma unroll
        for (int j = 0; j < 8; j += 4) {
            int col = bn + tx * 8 + j;
            float4 o;
            o.x = sigmoidf_(qi + g_q[col + 0] - 2.f * acc[i][j + 0]);
            o.y = sigmoidf_(qi + g_q[col + 1] - 2.f * acc[i][j + 1]);
            o.z = sigmoidf_(qi + g_q[col + 2] - 2.f * acc[i][j + 2]);
            o.w = sigmoidf_(qi + g_q[col + 3] - 2.f * acc[i][j + 3]);
            *reinterpret_cast<float4*>(&G[(size_t)row * Nn + col]) = o;
        }
    }
}

// ---------------- degree = row sums of G -------------------------------------
__global__ void k_rowsum(const float* __restrict__ G) {
    __shared__ float sh[8];
    int i = blockIdx.x, tid = threadIdx.x;
    const float* row = G + (size_t)i * Nn;
    float acc = 0.f;
    for (int t = tid; t < Nn; t += 256) acc += row[t];
    acc = blockReduceSumF(acc, sh);
    if (tid == 0) g_deg[i] = acc;
}

// ---------------- persistent Lanczos (entire m-step loop, 1 kernel) ----------
__global__ void __launch_bounds__(NT) k_lanczos(const float* __restrict__ G) {
    const int tid = threadIdx.x;
    const int gid = blockIdx.x * NT + tid;
    const int gw = gid >> 5, lane = gid & 31;

    // ---- init: zero scalars, build v1 = hash - mean, V0 = ones/sqrt(N)
    float r = 0.f;
    if (gid < Nn) {
        unsigned u = (unsigned)(gid + 1) * 2654435761u;
        u ^= u >> 16; u *= 2246822519u; u ^= u >> 13; u *= 3266489917u; u ^= u >> 16;
        r = (float)(u & 0xFFFFFFu) * (1.f / 16777216.f) - 0.5f;
        g_V[gid] = rsqrtf((float)Nn);
    }
    if (gid < M_LZ + 2) g_beta2[gid] = 0.f;
    if (gid == 0) g_mean = 0.f;
    gbar();
    if (gw < Nn / 32) {
        float s = warpReduceSumF(r);
        if (lane == 0) atomicAdd(&g_mean, s);
    }
    gbar();
    if (gid < Nn) g_w[gid] = r - g_mean * (1.f / (float)Nn);
    gbar();

    for (int j = 1; j <= M_LZ; j++) {
        // ---- Phase A: ubar = deg.*w - G*w (raw w); beta2[j] = ||w||^2
        if (gid < Nn) {
            float wv = g_w[gid];
            float p = warpReduceSumF(wv * wv);
            if (lane == 0) atomicAdd(&g_beta2[j], p);
        }
        {
            const float4* w4 = reinterpret_cast<const float4*>(g_w);
            for (int row = gw; row < Nn; row += NWARP) {
                const float4* Gr = reinterpret_cast<const float4*>(G + (size_t)row * Nn);
                float acc = 0.f;
#pragma unroll 4
                for (int t = lane; t < Nn / 4; t += 32) {
                    float4 gv = Gr[t], wv = w4[t];
                    acc += gv.x * wv.x + gv.y * wv.y + gv.z * wv.z + gv.w * wv.w;
                }
                acc = warpReduceSumF(acc);
                if (lane == 0) g_ub[row] = g_deg[row] * g_w[row] - acc;
            }
        }
        gbar();

        // ---- Phase B: commit V[j] = w*invb; u = ubar*invb; dots1 (scaled)
        float invb = rsqrtf(fmaxf(g_beta2[j], 1e-30f));
        if (gid < Nn) {
            float wv = g_w[gid];
            g_V[(size_t)j * Nn + gid] = wv * invb;
            g_u[gid] = g_ub[gid] * invb;
        }
        if (gw <= j) {
            const float4* ub4 = reinterpret_cast<const float4*>(g_ub);
            float acc = 0.f;
            if (gw == j) {
                const float4* w4 = reinterpret_cast<const float4*>(g_w);
#pragma unroll 4
                for (int t = lane; t < Nn / 4; t += 32) {
                    float4 a = w4[t], bq = ub4[t];
                    acc += a.x * bq.x + a.y * bq.y + a.z * bq.z + a.w * bq.w;
                }
                acc = warpReduceSumF(acc) * (invb * invb);
            } else {
                const float4* vi = reinterpret_cast<const float4*>(g_V + (size_t)gw * Nn);
#pragma unroll 4
                for (int t = lane; t < Nn / 4; t += 32) {
                    float4 a = vi[t], bq = ub4[t];
                    acc += a.x * bq.x + a.y * bq.y + a.z * bq.z + a.w * bq.w;
                }
                acc = warpReduceSumF(acc) * invb;
            }
            if (lane == 0) g_c1[gw] = acc;
        }
        gbar();

        // ---- Phase C: u -= sum_i c1_i V_i (16 stripes, atomics)
        {
            int s = gid >> 11, t = gid & (Nn - 1);
            if (gid < 16 * Nn) {
                float part = 0.f;
#pragma unroll 4
                for (int i = s; i <= j; i += 16)
                    part = fmaf(g_c1[i], g_V[(size_t)i * Nn + t], part);
                if (part != 0.f) atomicAdd(&g_u[t], -part);
            }
        }
        gbar();

        // ---- Phase D: dots2; pre-seed w = u
        if (gid < Nn) g_w[gid] = g_u[gid];
        if (gw <= j) {
            const float4* u4 = reinterpret_cast<const float4*>(g_u);
            const float4* vi = reinterpret_cast<const float4*>(g_V + (size_t)gw * Nn);
            float acc = 0.f;
#pragma unroll 4
            for (int t = lane; t < Nn / 4; t += 32) {
                float4 a = vi[t], bq = u4[t];
                acc += a.x * bq.x + a.y * bq.y + a.z * bq.z + a.w * bq.w;
            }
            acc = warpReduceSumF(acc);
            if (lane == 0) g_c2[gw] = acc;
        }
        gbar();

        // ---- Phase E: w -= sum_i c2_i V_i; alpha_j = c1_j + c2_j
        {
            int s = gid >> 11, t = gid & (Nn - 1);
            if (gid < 16 * Nn) {
                float part = 0.f;
#pragma unroll 4
                for (int i = s; i <= j; i += 16)
                    part = fmaf(g_c2[i], g_V[(size_t)i * Nn + t], part);
                if (part != 0.f) atomicAdd(&g_w[t], -part);
            }
            if (gid == 0) g_alpha[j] = g_c1[j] + g_c2[j];
        }
        gbar();
    }
}

// ---------------- smallest eigenpair of T (m tridiagonal), one warp ----------
__global__ void k_tridiag() {
    __shared__ double aa[M_LZ], bb2[M_LZ], bb[M_LZ];
    __shared__ double dw[M_LZ], ew[M_LZ], fw[M_LZ], yv[M_LZ], rv[M_LZ];
    __shared__ double sx[32];
    __shared__ int scnt[32];
    __shared__ double slo, shi;
    int lane = threadIdx.x;
    for (int i = lane; i < M_LZ; i += 32) {
        aa[i] = (double)g_alpha[i + 1];
        double b2 = (i < M_LZ - 1) ? (double)g_beta2[i + 2] : 0.0;
        bb2[i] = b2;
        bb[i] = sqrt(b2);
    }
    __syncwarp();
    if (lane == 0) {
        double lo = 1e300, hi = -1e300;
        for (int i = 0; i < M_LZ; i++) {
            double bl = (i > 0) ? bb[i - 1] : 0.0;
            double br = (i < M_LZ - 1) ? bb[i] : 0.0;
            lo = fmin(lo, aa[i] - bl - br);
            hi = fmax(hi, aa[i] + bl + br);
        }
        slo = lo - 1.0; shi = hi + 1.0;
    }
    __syncwarp();
    for (int round = 0; round < 8; round++) {
        double lo = slo, hi = shi;
        double x = lo + (hi - lo) * (double)(lane + 1) * (1.0 / 33.0);
        double d = aa[0] - x;
        int cnt = (d < 0.0);
        for (int i = 1; i < M_LZ; i++) {
            if (fabs(d) < 1e-280) d = (d < 0.0 ? -1e-280 : 1e-280);
            d = aa[i] - x - bb2[i - 1] / d;
            cnt += (d < 0.0);
        }
        sx[lane] = x; scnt[lane] = cnt;
        __syncwarp();
        if (lane == 0) {
            double nlo = lo, nhi = hi;
            int k = 0;
            while (k < 32 && scnt[k] < 1) k++;
            if (k < 32) { nhi = sx[k]; if (k > 0) nlo = sx[k - 1]; }
            else        { nlo = sx[31]; }
            slo = nlo; shi = nhi;
        }
        __syncwarp();
    }
    double th = 0.5 * (slo + shi);
    if (lane == 0) {
        for (int i = 0; i < M_LZ; i++) rv[i] = 1.0;
        for (int it = 0; it < 3; it++) {
            for (int i = 0; i < M_LZ; i++) {
                dw[i] = aa[i] - th;
                ew[i] = (i < M_LZ - 1) ? bb[i] : 0.0;
                fw[i] = 0.0;
                yv[i] = rv[i];
            }
            for (int i = 0; i < M_LZ - 1; i++) {
                double s = bb[i];
                if (fabs(s) > fabs(dw[i])) {
                    double od = dw[i], oe = ew[i], of = fw[i];
                    dw[i] = s;       ew[i] = dw[i + 1]; fw[i] = ew[i + 1];
                    s = od;          dw[i + 1] = oe;    ew[i + 1] = of;
                    double ry = yv[i]; yv[i] = yv[i + 1]; yv[i + 1] = ry;
                }
                double p = dw[i];
                if (fabs(p) < 1e-280) { p = (p < 0.0 ? -1e-280 : 1e-280); dw[i] = p; }
                double m = s / p;
                dw[i + 1] -= m * ew[i];
                ew[i + 1] -= m * fw[i];
                yv[i + 1] -= m * yv[i];
            }
            for (int i = M_LZ - 1; i >= 0; i--) {
                double v = yv[i];
                if (i + 1 < M_LZ) v -= ew[i] * yv[i + 1];
                if (i + 2 < M_LZ) v -= fw[i] * yv[i + 2];
                double p = dw[i];
                if (fabs(p) < 1e-280) p = (p < 0.0 ? -1e-280 : 1e-280);
                yv[i] = v / p;
            }
            double n2 = 0.0;
            for (int i = 0; i < M_LZ; i++) n2 += yv[i] * yv[i];
            double inv = 1.0 / sqrt(n2);
            for (int i = 0; i < M_LZ; i++) rv[i] = yv[i] * inv;
        }
        for (int i = 0; i < M_LZ; i++) g_yd[i] = rv[i];
    }
}

// ---------------- fv = sum_r y_{r-1} V[r] -------------------------------------
__global__ void k_assemble() {
    int t = blockIdx.x * 256 + threadIdx.x;
    float acc = 0.f;
    for (int rr = 1; rr <= M_LZ; rr++)
        acc = fmaf((float)g_yd[rr - 1], g_V[(size_t)rr * Nn + t], acc);
    g_fv[t] = acc;
}

// ---------------- z = L * fv (fp32) -------------------------------------------
__global__ void k_rq(const float* __restrict__ G) {
    __shared__ float sh[8];
    int i = blockIdx.x, tid = threadIdx.x;
    const float* row = G + (size_t)i * Nn;
    float acc = 0.f;
    for (int t = tid; t < Nn; t += 256) acc = fmaf(row[t], g_fv[t], acc);
    acc = blockReduceSumF(acc, sh);
    if (tid == 0) g_z[i] = g_deg[i] * g_fv[i] - acc;
}

// ---------------- value = fv.z / fv.fv; normalize + sign + write --------------
__global__ void k_final(float* __restrict__ out) {
    __shared__ double sh[32];
    __shared__ float sabs[32];
    __shared__ int sidx[32];
    __shared__ double ssign;
    int tid = threadIdx.x;
    double a = (double)g_fv[tid], b = (double)g_fv[tid + 1024];
    double num = blockReduceSumD(a * (double)g_z[tid] + b * (double)g_z[tid + 1024], sh);
    double den = blockReduceSumD(a * a + b * b, sh);
    float bav; int bix;
    float fa = (float)fabs(a), fb = (float)fabs(b);
    if (fa >= fb) { bav = fa; bix = tid; }
    else          { bav = fb; bix = tid + 1024; }
#pragma unroll
    for (int o = 16; o; o >>= 1) {
        float ov = __shfl_down_sync(0xffffffffu, bav, o);
        int   oi = __shfl_down_sync(0xffffffffu, bix, o);
        if (ov > bav || (ov == bav && oi < bix)) { bav = ov; bix = oi; }
    }
    int lane = tid & 31, wid = tid >> 5;
    if (lane == 0) { sabs[wid] = bav; sidx[wid] = bix; }
    __syncthreads();
    if (tid == 0) {
        float bv = sabs[0]; int bi = sidx[0];
        for (int i = 1; i < 32; i++)
            if (sabs[i] > bv || (sabs[i] == bv && sidx[i] < bi)) { bv = sabs[i]; bi = sidx[i]; }
        ssign = (g_fv[bi] >= 0.f ? 1.0 : -1.0) * SIGN_CONV;
        out[(size_t)Nn * Nn] = (float)(num / fmax(den, 1e-300));
    }
    __syncthreads();
    double sc = ssign / sqrt(fmax(den, 1e-300));
    size_t base = (size_t)Nn * Nn + 1;
    out[base + tid]        = (float)(a * sc);
    out[base + tid + 1024] = (float)(b * sc);
}

// ---------------- launcher ----------------------------------------------------
extern "C" void kernel_launch(void* const* d_in, const int* in_sizes, int n_in,
                              void* d_out, int out_size) {
    const float* x = (const float*)d_in[0];
    const float* w = (const float*)d_in[1];
    const float* b = (const float*)d_in[2];
    float* out = (float*)d_out;
    float* G = out;   // grouping matrix lives at the front of d_out

    k_q<<<Nn, 128>>>(x, w);
    k_gemm<<<dim3(Nn / 128, Nn / 128), 256>>>(x, w, b, G);
    k_rowsum<<<Nn, 256>>>(G);
    k_lanczos<<<NB, NT>>>(G);
    k_tridiag<<<1, 32>>>();
    k_assemble<<<Nn / 256, 256>>>();
    k_rq<<<Nn, 256>>>(G);
    k_final<<<1, 1024>>>(out);
}